// round 16
// baseline (speedup 1.0000x reference)
#include <cuda_runtime.h>
#include <cuda_bf16.h>

// LSTM_24936580121326 R16: R9 (constant gate-pair f32x2, 2 elem/thread) with
// (a) .64 constant loads packed into .128 (wx/b1/b2 pairs -> ulonglong2),
// (b) explicit ping-pong t-loop (2 steps/iter) to remove state-copy MOVs.

#define T_STEPS 49

typedef unsigned long long u64;

struct WPack {
    ulonglong2 w1if[8][4];   // layer1 W_hh rows (i,f) scaled 0.5
    ulonglong2 w1go[8][4];   // layer1 W_hh rows (g unscaled, o 0.5)
    ulonglong2 w2uif[8][4];  // layer2 W_ih
    ulonglong2 w2ugo[8][4];
    ulonglong2 w2vif[8][4];  // layer2 W_hh
    ulonglong2 w2vgo[8][4];
    ulonglong2 wx[8];        // {wx_if_pair, wx_go_pair}
    ulonglong2 b1[8];        // {b1if_pair, b1go_pair}
    ulonglong2 b2[8];        // {b2if_pair, b2go_pair}
    float wlin[8];
    float blin;
};

__device__   WPack g_wtmp;
__constant__ WPack c_w;

__device__ __forceinline__ u64 pack2(float lo, float hi) {
    u64 r; asm("mov.b64 %0, {%1, %2};" : "=l"(r) : "f"(lo), "f"(hi)); return r;
}
__device__ __forceinline__ void unpack2(u64 v, float& lo, float& hi) {
    asm("mov.b64 {%0, %1}, %2;" : "=f"(lo), "=f"(hi) : "l"(v));
}
__device__ __forceinline__ u64 fma2(u64 a, u64 b, u64 c) {
    u64 d; asm("fma.rn.f32x2 %0, %1, %2, %3;" : "=l"(d) : "l"(a), "l"(b), "l"(c)); return d;
}
__device__ __forceinline__ float tanhf_hw(float x) {
    float y; asm("tanh.approx.f32 %0, %1;" : "=f"(y) : "f"(x)); return y;
}
__device__ __forceinline__ float sig_folded(float zh) {   // pre-halved input
    return fmaf(0.5f, tanhf_hw(zh), 0.5f);
}

// ---------------- preproc ----------------
__global__ void prep_weights_kernel(
    const float* __restrict__ W_ih0, const float* __restrict__ W_hh0,
    const float* __restrict__ b_ih0, const float* __restrict__ b_hh0,
    const float* __restrict__ W_ih1, const float* __restrict__ W_hh1,
    const float* __restrict__ b_ih1, const float* __restrict__ b_hh1,
    const float* __restrict__ W_lin, const float* __restrict__ b_lin)
{
    int tid = threadIdx.x;
    if (tid < 128) {
        int u = tid >> 4, q = (tid >> 2) & 3, s = tid & 3;
        int col = 2 * q + (s >> 1);
        int sel = s & 1;
        int idx = (u * 4 + q) * 4 + s;
        int gIF = u + 8 * sel;           // i or f
        int gGO = u + 16 + 8 * sel;      // g or o
        float scGO = sel ? 0.5f : 1.0f;
        ((float*)g_wtmp.w1if)[idx]  = 0.5f * W_hh0[gIF * 8 + col];
        ((float*)g_wtmp.w1go)[idx]  = scGO * W_hh0[gGO * 8 + col];
        ((float*)g_wtmp.w2uif)[idx] = 0.5f * W_ih1[gIF * 8 + col];
        ((float*)g_wtmp.w2ugo)[idx] = scGO * W_ih1[gGO * 8 + col];
        ((float*)g_wtmp.w2vif)[idx] = 0.5f * W_hh1[gIF * 8 + col];
        ((float*)g_wtmp.w2vgo)[idx] = scGO * W_hh1[gGO * 8 + col];
    }
    if (tid < 8) {
        int u = tid;
        float* p;
        p = (float*)&g_wtmp.wx[u];
        p[0] = 0.5f * W_ih0[u];      p[1] = 0.5f * W_ih0[u + 8];
        p[2] =        W_ih0[u + 16]; p[3] = 0.5f * W_ih0[u + 24];
        p = (float*)&g_wtmp.b1[u];
        p[0] = 0.5f * (b_ih0[u]      + b_hh0[u]);
        p[1] = 0.5f * (b_ih0[u + 8]  + b_hh0[u + 8]);
        p[2] =        (b_ih0[u + 16] + b_hh0[u + 16]);
        p[3] = 0.5f * (b_ih0[u + 24] + b_hh0[u + 24]);
        p = (float*)&g_wtmp.b2[u];
        p[0] = 0.5f * (b_ih1[u]      + b_hh1[u]);
        p[1] = 0.5f * (b_ih1[u + 8]  + b_hh1[u + 8]);
        p[2] =        (b_ih1[u + 16] + b_hh1[u + 16]);
        p[3] = 0.5f * (b_ih1[u + 24] + b_hh1[u + 24]);
        g_wtmp.wlin[u] = W_lin[u];
    }
    if (tid == 0) g_wtmp.blin = b_lin[0];
}

// One full timestep (both layers, both elements). Inlined; array refs keep
// everything register-resident after SROA.
__device__ __forceinline__ void lstm_step(
    u64 xxA, u64 xxB,
    const u64 (&hp1A)[8], const u64 (&hp1B)[8],
    const u64 (&hp2A)[8], const u64 (&hp2B)[8],
    u64 (&hn1A)[8], u64 (&hn1B)[8],
    u64 (&hn2A)[8], u64 (&hn2B)[8],
    float (&c1A)[8], float (&c1B)[8],
    float (&c2A)[8], float (&c2B)[8])
{
    // ---------- layer 1 ----------
#pragma unroll
    for (int u = 0; u < 8; ++u) {
        ulonglong2 wxu = c_w.wx[u];
        ulonglong2 b1u = c_w.b1[u];
        u64 aifA = fma2(wxu.x, xxA, b1u.x);
        u64 agoA = fma2(wxu.y, xxA, b1u.y);
        u64 aifB = fma2(wxu.x, xxB, b1u.x);
        u64 agoB = fma2(wxu.y, xxB, b1u.y);
#pragma unroll
        for (int q = 0; q < 4; ++q) {
            ulonglong2 wi = c_w.w1if[u][q];
            ulonglong2 wg = c_w.w1go[u][q];
            aifA = fma2(wi.x, hp1A[2*q],   aifA);
            aifA = fma2(wi.y, hp1A[2*q+1], aifA);
            agoA = fma2(wg.x, hp1A[2*q],   agoA);
            agoA = fma2(wg.y, hp1A[2*q+1], agoA);
            aifB = fma2(wi.x, hp1B[2*q],   aifB);
            aifB = fma2(wi.y, hp1B[2*q+1], aifB);
            agoB = fma2(wg.x, hp1B[2*q],   agoB);
            agoB = fma2(wg.y, hp1B[2*q+1], agoB);
        }
        {
            float zi, zf, zg, zo;
            unpack2(aifA, zi, zf);
            unpack2(agoA, zg, zo);
            float ig = sig_folded(zi), fg = sig_folded(zf);
            float gg = tanhf_hw(zg),  og = sig_folded(zo);
            c1A[u] = fmaf(fg, c1A[u], ig * gg);
            float h = og * tanhf_hw(c1A[u]);
            hn1A[u] = pack2(h, h);
        }
        {
            float zi, zf, zg, zo;
            unpack2(aifB, zi, zf);
            unpack2(agoB, zg, zo);
            float ig = sig_folded(zi), fg = sig_folded(zf);
            float gg = tanhf_hw(zg),  og = sig_folded(zo);
            c1B[u] = fmaf(fg, c1B[u], ig * gg);
            float h = og * tanhf_hw(c1B[u]);
            hn1B[u] = pack2(h, h);
        }
    }

    // ---------- layer 2 ----------
#pragma unroll
    for (int u = 0; u < 8; ++u) {
        ulonglong2 b2u = c_w.b2[u];
        u64 aifA = b2u.x, agoA = b2u.y;
        u64 aifB = b2u.x, agoB = b2u.y;
#pragma unroll
        for (int q = 0; q < 4; ++q) {
            ulonglong2 ui = c_w.w2uif[u][q];
            ulonglong2 ug = c_w.w2ugo[u][q];
            aifA = fma2(ui.x, hn1A[2*q],   aifA);
            aifA = fma2(ui.y, hn1A[2*q+1], aifA);
            agoA = fma2(ug.x, hn1A[2*q],   agoA);
            agoA = fma2(ug.y, hn1A[2*q+1], agoA);
            aifB = fma2(ui.x, hn1B[2*q],   aifB);
            aifB = fma2(ui.y, hn1B[2*q+1], aifB);
            agoB = fma2(ug.x, hn1B[2*q],   agoB);
            agoB = fma2(ug.y, hn1B[2*q+1], agoB);
        }
#pragma unroll
        for (int q = 0; q < 4; ++q) {
            ulonglong2 vi = c_w.w2vif[u][q];
            ulonglong2 vg = c_w.w2vgo[u][q];
            aifA = fma2(vi.x, hp2A[2*q],   aifA);
            aifA = fma2(vi.y, hp2A[2*q+1], aifA);
            agoA = fma2(vg.x, hp2A[2*q],   agoA);
            agoA = fma2(vg.y, hp2A[2*q+1], agoA);
            aifB = fma2(vi.x, hp2B[2*q],   aifB);
            aifB = fma2(vi.y, hp2B[2*q+1], aifB);
            agoB = fma2(vg.x, hp2B[2*q],   agoB);
            agoB = fma2(vg.y, hp2B[2*q+1], agoB);
        }
        {
            float zi, zf, zg, zo;
            unpack2(aifA, zi, zf);
            unpack2(agoA, zg, zo);
            float ig = sig_folded(zi), fg = sig_folded(zf);
            float gg = tanhf_hw(zg),  og = sig_folded(zo);
            c2A[u] = fmaf(fg, c2A[u], ig * gg);
            float h = og * tanhf_hw(c2A[u]);
            hn2A[u] = pack2(h, h);
        }
        {
            float zi, zf, zg, zo;
            unpack2(aifB, zi, zf);
            unpack2(agoB, zg, zo);
            float ig = sig_folded(zi), fg = sig_folded(zf);
            float gg = tanhf_hw(zg),  og = sig_folded(zo);
            c2B[u] = fmaf(fg, c2B[u], ig * gg);
            float h = og * tanhf_hw(c2B[u]);
            hn2B[u] = pack2(h, h);
        }
    }
}

// ---------------- fused LSTM: ping-pong steps, 2 elements/thread -----------
__global__ void __launch_bounds__(256) lstm_fused_kernel(
    const float* __restrict__ X, float* __restrict__ out, int Bn)
{
    int tid  = threadIdx.x;
    int bA = blockIdx.x * 512 + tid;
    int bB = bA + 256;
    bool vA = bA < Bn, vB = bB < Bn;

    u64 P1A[8], P1B[8], P2A[8], P2B[8];   // ping state {h,h}
    u64 Q1A[8], Q1B[8], Q2A[8], Q2B[8];   // pong state
    float c1A[8], c1B[8], c2A[8], c2B[8];
    u64 zero = pack2(0.f, 0.f);
#pragma unroll
    for (int u = 0; u < 8; ++u) {
        P1A[u] = P1B[u] = P2A[u] = P2B[u] = zero;
        c1A[u] = c1B[u] = c2A[u] = c2B[u] = 0.f;
    }

    const float* __restrict__ xpA = X + (long long)(vA ? bA : 0) * T_STEPS;
    const float* __restrict__ xpB = X + (long long)(vB ? bB : 0) * T_STEPS;

#pragma unroll 1
    for (int it = 0; it < 24; ++it) {
        int t = 2 * it;
        {
            float xA = __ldg(xpA + t), xB = __ldg(xpB + t);
            lstm_step(pack2(xA, xA), pack2(xB, xB),
                      P1A, P1B, P2A, P2B,
                      Q1A, Q1B, Q2A, Q2B,
                      c1A, c1B, c2A, c2B);
        }
        {
            float xA = __ldg(xpA + t + 1), xB = __ldg(xpB + t + 1);
            lstm_step(pack2(xA, xA), pack2(xB, xB),
                      Q1A, Q1B, Q2A, Q2B,
                      P1A, P1B, P2A, P2B,
                      c1A, c1B, c2A, c2B);
        }
    }
    // final step t = 48 (results land in Q)
    {
        float xA = __ldg(xpA + 48), xB = __ldg(xpB + 48);
        lstm_step(pack2(xA, xA), pack2(xB, xB),
                  P1A, P1B, P2A, P2B,
                  Q1A, Q1B, Q2A, Q2B,
                  c1A, c1B, c2A, c2B);
    }

    // ---------- relu -> linear -> relu ----------
    float accA = c_w.blin, accB = c_w.blin;
#pragma unroll
    for (int u = 0; u < 8; ++u) {
        float hA, hB, d;
        unpack2(Q2A[u], hA, d);
        unpack2(Q2B[u], hB, d);
        accA = fmaf(c_w.wlin[u], fmaxf(hA, 0.0f), accA);
        accB = fmaf(c_w.wlin[u], fmaxf(hB, 0.0f), accB);
    }
    if (vA) out[bA] = fmaxf(accA, 0.0f);
    if (vB) out[bB] = fmaxf(accB, 0.0f);
}

extern "C" void kernel_launch(void* const* d_in, const int* in_sizes, int n_in,
                              void* d_out, int out_size) {
    const float* X     = (const float*)d_in[0];
    const float* W_ih0 = (const float*)d_in[1];
    const float* W_hh0 = (const float*)d_in[2];
    const float* b_ih0 = (const float*)d_in[3];
    const float* b_hh0 = (const float*)d_in[4];
    const float* W_ih1 = (const float*)d_in[5];
    const float* W_hh1 = (const float*)d_in[6];
    const float* b_ih1 = (const float*)d_in[7];
    const float* b_hh1 = (const float*)d_in[8];
    const float* W_lin = (const float*)d_in[9];
    const float* b_lin = (const float*)d_in[10];

    int Bn = out_size;

    prep_weights_kernel<<<1, 256>>>(
        W_ih0, W_hh0, b_ih0, b_hh0,
        W_ih1, W_hh1, b_ih1, b_hh1, W_lin, b_lin);

    void* src = nullptr;
    cudaGetSymbolAddress(&src, g_wtmp);
    cudaMemcpyToSymbolAsync(c_w, src, sizeof(WPack), 0,
                            cudaMemcpyDeviceToDevice, 0);

    int blocks = (Bn + 511) / 512;
    lstm_fused_kernel<<<blocks, 256>>>(X, (float*)d_out, Bn);
}

// round 17
// speedup vs baseline: 3.1716x; 3.1716x over previous
#include <cuda_runtime.h>
#include <cuda_bf16.h>

// LSTM_24936580121326 R17: R9 EXACT structure (constant gate-pair f32x2,
// 2 elem/thread, sequential t-loop with state copies) + single safe delta:
// wx/b1/b2 stored as ulonglong2 so each unit issues 1 LDC.128 instead of
// 2-4 LDC.64 (constant port is the proven binder; R16's ping-pong removed).

#define T_STEPS 49

typedef unsigned long long u64;

struct WPack {
    ulonglong2 w1if[8][4];   // layer1 W_hh rows (i,f) scaled 0.5
    ulonglong2 w1go[8][4];   // layer1 W_hh rows (g unscaled, o 0.5)
    ulonglong2 w2uif[8][4];  // layer2 W_ih
    ulonglong2 w2ugo[8][4];
    ulonglong2 w2vif[8][4];  // layer2 W_hh
    ulonglong2 w2vgo[8][4];
    ulonglong2 wx[8];        // {wx_if_pair, wx_go_pair}
    ulonglong2 b1[8];        // {b1if_pair, b1go_pair}
    ulonglong2 b2[8];        // {b2if_pair, b2go_pair}
    float wlin[8];
    float blin;
};

__device__   WPack g_wtmp;
__constant__ WPack c_w;

__device__ __forceinline__ u64 pack2(float lo, float hi) {
    u64 r; asm("mov.b64 %0, {%1, %2};" : "=l"(r) : "f"(lo), "f"(hi)); return r;
}
__device__ __forceinline__ void unpack2(u64 v, float& lo, float& hi) {
    asm("mov.b64 {%0, %1}, %2;" : "=f"(lo), "=f"(hi) : "l"(v));
}
__device__ __forceinline__ u64 fma2(u64 a, u64 b, u64 c) {
    u64 d; asm("fma.rn.f32x2 %0, %1, %2, %3;" : "=l"(d) : "l"(a), "l"(b), "l"(c)); return d;
}
__device__ __forceinline__ float tanhf_hw(float x) {
    float y; asm("tanh.approx.f32 %0, %1;" : "=f"(y) : "f"(x)); return y;
}
__device__ __forceinline__ float sig_folded(float zh) {   // pre-halved input
    return fmaf(0.5f, tanhf_hw(zh), 0.5f);
}

// ---------------- preproc ----------------
__global__ void prep_weights_kernel(
    const float* __restrict__ W_ih0, const float* __restrict__ W_hh0,
    const float* __restrict__ b_ih0, const float* __restrict__ b_hh0,
    const float* __restrict__ W_ih1, const float* __restrict__ W_hh1,
    const float* __restrict__ b_ih1, const float* __restrict__ b_hh1,
    const float* __restrict__ W_lin, const float* __restrict__ b_lin)
{
    int tid = threadIdx.x;
    if (tid < 128) {
        int u = tid >> 4, q = (tid >> 2) & 3, s = tid & 3;
        int col = 2 * q + (s >> 1);
        int sel = s & 1;
        int idx = (u * 4 + q) * 4 + s;
        int gIF = u + 8 * sel;           // i or f
        int gGO = u + 16 + 8 * sel;      // g or o
        float scGO = sel ? 0.5f : 1.0f;
        ((float*)g_wtmp.w1if)[idx]  = 0.5f * W_hh0[gIF * 8 + col];
        ((float*)g_wtmp.w1go)[idx]  = scGO * W_hh0[gGO * 8 + col];
        ((float*)g_wtmp.w2uif)[idx] = 0.5f * W_ih1[gIF * 8 + col];
        ((float*)g_wtmp.w2ugo)[idx] = scGO * W_ih1[gGO * 8 + col];
        ((float*)g_wtmp.w2vif)[idx] = 0.5f * W_hh1[gIF * 8 + col];
        ((float*)g_wtmp.w2vgo)[idx] = scGO * W_hh1[gGO * 8 + col];
    }
    if (tid < 8) {
        int u = tid;
        float* p;
        p = (float*)&g_wtmp.wx[u];
        p[0] = 0.5f * W_ih0[u];      p[1] = 0.5f * W_ih0[u + 8];
        p[2] =        W_ih0[u + 16]; p[3] = 0.5f * W_ih0[u + 24];
        p = (float*)&g_wtmp.b1[u];
        p[0] = 0.5f * (b_ih0[u]      + b_hh0[u]);
        p[1] = 0.5f * (b_ih0[u + 8]  + b_hh0[u + 8]);
        p[2] =        (b_ih0[u + 16] + b_hh0[u + 16]);
        p[3] = 0.5f * (b_ih0[u + 24] + b_hh0[u + 24]);
        p = (float*)&g_wtmp.b2[u];
        p[0] = 0.5f * (b_ih1[u]      + b_hh1[u]);
        p[1] = 0.5f * (b_ih1[u + 8]  + b_hh1[u + 8]);
        p[2] =        (b_ih1[u + 16] + b_hh1[u + 16]);
        p[3] = 0.5f * (b_ih1[u + 24] + b_hh1[u + 24]);
        g_wtmp.wlin[u] = W_lin[u];
    }
    if (tid == 0) g_wtmp.blin = b_lin[0];
}

// ---------------- fused LSTM: 2 elements per thread (R9 structure) ---------
__global__ void __launch_bounds__(256) lstm_fused_kernel(
    const float* __restrict__ X, float* __restrict__ out, int Bn)
{
    int tid  = threadIdx.x;
    int bA = blockIdx.x * 512 + tid;
    int bB = bA + 256;
    bool vA = bA < Bn, vB = bB < Bn;

    u64 hp1A[8], hp2A[8], hp1B[8], hp2B[8];   // {h,h} splats
    float c1A[8], c2A[8], c1B[8], c2B[8];
    u64 zero = pack2(0.f, 0.f);
#pragma unroll
    for (int u = 0; u < 8; ++u) {
        hp1A[u] = hp2A[u] = hp1B[u] = hp2B[u] = zero;
        c1A[u] = c2A[u] = c1B[u] = c2B[u] = 0.f;
    }

    const float* __restrict__ xpA = X + (long long)(vA ? bA : 0) * T_STEPS;
    const float* __restrict__ xpB = X + (long long)(vB ? bB : 0) * T_STEPS;

    for (int t = 0; t < T_STEPS; ++t) {
        float xA = __ldg(xpA + t);
        float xB = __ldg(xpB + t);
        u64 xxA = pack2(xA, xA);
        u64 xxB = pack2(xB, xB);

        // ---------- layer 1 ----------
        u64 hn1A[8], hn1B[8];
#pragma unroll
        for (int u = 0; u < 8; ++u) {
            ulonglong2 wxu = c_w.wx[u];    // 1x LDC.128
            ulonglong2 b1u = c_w.b1[u];    // 1x LDC.128
            u64 aifA = fma2(wxu.x, xxA, b1u.x);
            u64 agoA = fma2(wxu.y, xxA, b1u.y);
            u64 aifB = fma2(wxu.x, xxB, b1u.x);
            u64 agoB = fma2(wxu.y, xxB, b1u.y);
#pragma unroll
            for (int q = 0; q < 4; ++q) {
                ulonglong2 wi = c_w.w1if[u][q];
                ulonglong2 wg = c_w.w1go[u][q];
                aifA = fma2(wi.x, hp1A[2*q],   aifA);
                aifA = fma2(wi.y, hp1A[2*q+1], aifA);
                agoA = fma2(wg.x, hp1A[2*q],   agoA);
                agoA = fma2(wg.y, hp1A[2*q+1], agoA);
                aifB = fma2(wi.x, hp1B[2*q],   aifB);
                aifB = fma2(wi.y, hp1B[2*q+1], aifB);
                agoB = fma2(wg.x, hp1B[2*q],   agoB);
                agoB = fma2(wg.y, hp1B[2*q+1], agoB);
            }
            {
                float zi, zf, zg, zo;
                unpack2(aifA, zi, zf);
                unpack2(agoA, zg, zo);
                float ig = sig_folded(zi), fg = sig_folded(zf);
                float gg = tanhf_hw(zg),  og = sig_folded(zo);
                c1A[u] = fmaf(fg, c1A[u], ig * gg);
                float h = og * tanhf_hw(c1A[u]);
                hn1A[u] = pack2(h, h);
            }
            {
                float zi, zf, zg, zo;
                unpack2(aifB, zi, zf);
                unpack2(agoB, zg, zo);
                float ig = sig_folded(zi), fg = sig_folded(zf);
                float gg = tanhf_hw(zg),  og = sig_folded(zo);
                c1B[u] = fmaf(fg, c1B[u], ig * gg);
                float h = og * tanhf_hw(c1B[u]);
                hn1B[u] = pack2(h, h);
            }
        }

        // ---------- layer 2 ----------
        u64 hn2A[8], hn2B[8];
#pragma unroll
        for (int u = 0; u < 8; ++u) {
            ulonglong2 b2u = c_w.b2[u];    // 1x LDC.128
            u64 aifA = b2u.x, agoA = b2u.y;
            u64 aifB = b2u.x, agoB = b2u.y;
#pragma unroll
            for (int q = 0; q < 4; ++q) {
                ulonglong2 ui = c_w.w2uif[u][q];
                ulonglong2 ug = c_w.w2ugo[u][q];
                aifA = fma2(ui.x, hn1A[2*q],   aifA);
                aifA = fma2(ui.y, hn1A[2*q+1], aifA);
                agoA = fma2(ug.x, hn1A[2*q],   agoA);
                agoA = fma2(ug.y, hn1A[2*q+1], agoA);
                aifB = fma2(ui.x, hn1B[2*q],   aifB);
                aifB = fma2(ui.y, hn1B[2*q+1], aifB);
                agoB = fma2(ug.x, hn1B[2*q],   agoB);
                agoB = fma2(ug.y, hn1B[2*q+1], agoB);
            }
#pragma unroll
            for (int q = 0; q < 4; ++q) {
                ulonglong2 vi = c_w.w2vif[u][q];
                ulonglong2 vg = c_w.w2vgo[u][q];
                aifA = fma2(vi.x, hp2A[2*q],   aifA);
                aifA = fma2(vi.y, hp2A[2*q+1], aifA);
                agoA = fma2(vg.x, hp2A[2*q],   agoA);
                agoA = fma2(vg.y, hp2A[2*q+1], agoA);
                aifB = fma2(vi.x, hp2B[2*q],   aifB);
                aifB = fma2(vi.y, hp2B[2*q+1], aifB);
                agoB = fma2(vg.x, hp2B[2*q],   agoB);
                agoB = fma2(vg.y, hp2B[2*q+1], agoB);
            }
            {
                float zi, zf, zg, zo;
                unpack2(aifA, zi, zf);
                unpack2(agoA, zg, zo);
                float ig = sig_folded(zi), fg = sig_folded(zf);
                float gg = tanhf_hw(zg),  og = sig_folded(zo);
                c2A[u] = fmaf(fg, c2A[u], ig * gg);
                float h = og * tanhf_hw(c2A[u]);
                hn2A[u] = pack2(h, h);
            }
            {
                float zi, zf, zg, zo;
                unpack2(aifB, zi, zf);
                unpack2(agoB, zg, zo);
                float ig = sig_folded(zi), fg = sig_folded(zf);
                float gg = tanhf_hw(zg),  og = sig_folded(zo);
                c2B[u] = fmaf(fg, c2B[u], ig * gg);
                float h = og * tanhf_hw(c2B[u]);
                hn2B[u] = pack2(h, h);
            }
        }

#pragma unroll
        for (int u = 0; u < 8; ++u) {
            hp1A[u] = hn1A[u]; hp2A[u] = hn2A[u];
            hp1B[u] = hn1B[u]; hp2B[u] = hn2B[u];
        }
    }

    // ---------- relu -> linear -> relu ----------
    float accA = c_w.blin, accB = c_w.blin;
#pragma unroll
    for (int u = 0; u < 8; ++u) {
        float hA, hB, d;
        unpack2(hp2A[u], hA, d);
        unpack2(hp2B[u], hB, d);
        accA = fmaf(c_w.wlin[u], fmaxf(hA, 0.0f), accA);
        accB = fmaf(c_w.wlin[u], fmaxf(hB, 0.0f), accB);
    }
    if (vA) out[bA] = fmaxf(accA, 0.0f);
    if (vB) out[bB] = fmaxf(accB, 0.0f);
}

extern "C" void kernel_launch(void* const* d_in, const int* in_sizes, int n_in,
                              void* d_out, int out_size) {
    const float* X     = (const float*)d_in[0];
    const float* W_ih0 = (const float*)d_in[1];
    const float* W_hh0 = (const float*)d_in[2];
    const float* b_ih0 = (const float*)d_in[3];
    const float* b_hh0 = (const float*)d_in[4];
    const float* W_ih1 = (const float*)d_in[5];
    const float* W_hh1 = (const float*)d_in[6];
    const float* b_ih1 = (const float*)d_in[7];
    const float* b_hh1 = (const float*)d_in[8];
    const float* W_lin = (const float*)d_in[9];
    const float* b_lin = (const float*)d_in[10];

    int Bn = out_size;

    prep_weights_kernel<<<1, 256>>>(
        W_ih0, W_hh0, b_ih0, b_hh0,
        W_ih1, W_hh1, b_ih1, b_hh1, W_lin, b_lin);

    void* src = nullptr;
    cudaGetSymbolAddress(&src, g_wtmp);
    cudaMemcpyToSymbolAsync(c_w, src, sizeof(WPack), 0,
                            cudaMemcpyDeviceToDevice, 0);

    int blocks = (Bn + 511) / 512;
    lstm_fused_kernel<<<blocks, 256>>>(X, (float*)d_out, Bn);
}